// round 17
// baseline (speedup 1.0000x reference)
#include <cuda_runtime.h>
#include <cuda_fp16.h>
#include <math.h>
#include <stdint.h>

#define B_  4
#define S_  2048
#define D_  1024
#define H_  16
#define HD_ 64
#define M_  (B_ * S_)
#define NTOT (B_ * S_ * D_)

// Scratch (allocation-free rule: __device__ globals)
__device__ __half g_x3[3 * NTOT];        // packed Q16, K16, V16 inputs
__device__ __half g_wqkv[3 * D_ * D_];   // packed Wq, Wk, Wv fp16
__device__ __half g_w16[D_ * D_];        // Wo fp16
__device__ __half g_q16[NTOT];
__device__ __half g_k16[NTOT];
__device__ __half g_v16[NTOT];
__device__ __half g_o16[NTOT];
__device__ float2 g_rope[S_ * 32];

// ===========================================================================
// Helpers (baseline PTX only — compute_103-safe)
// ===========================================================================
__device__ __forceinline__ uint32_t smem_to_u32(const void* p) {
    uint32_t a;
    asm("{ .reg .u64 t; cvta.to.shared.u64 t, %1; cvt.u32.u64 %0, t; }" : "=r"(a) : "l"(p));
    return a;
}
#define SMEM_SWIZZLE_128B(off) ((off) ^ (((off) >> 3) & 0x70))

__device__ __forceinline__ void cpa16(uint32_t dst, const void* src) {
    asm volatile("cp.async.cg.shared.global [%0], [%1], 16;" :: "r"(dst), "l"(src));
}
__device__ __forceinline__ void ldsm4(uint32_t& r0, uint32_t& r1, uint32_t& r2, uint32_t& r3,
                                      uint32_t addr) {
    asm volatile("ldmatrix.sync.aligned.m8n8.x4.shared.b16 {%0,%1,%2,%3}, [%4];"
        : "=r"(r0), "=r"(r1), "=r"(r2), "=r"(r3) : "r"(addr));
}
__device__ __forceinline__ void ldsm4t(uint32_t& r0, uint32_t& r1, uint32_t& r2, uint32_t& r3,
                                       uint32_t addr) {
    asm volatile("ldmatrix.sync.aligned.m8n8.x4.trans.shared.b16 {%0,%1,%2,%3}, [%4];"
        : "=r"(r0), "=r"(r1), "=r"(r2), "=r"(r3) : "r"(addr));
}
__device__ __forceinline__ void mma_fp16(float* d, const uint32_t* a,
                                         uint32_t b0, uint32_t b1) {
    asm volatile(
        "mma.sync.aligned.m16n8k16.row.col.f32.f16.f16.f32 "
        "{%0,%1,%2,%3}, {%4,%5,%6,%7}, {%8,%9}, {%0,%1,%2,%3};"
        : "+f"(d[0]), "+f"(d[1]), "+f"(d[2]), "+f"(d[3])
        : "r"(a[0]), "r"(a[1]), "r"(a[2]), "r"(a[3]), "r"(b0), "r"(b1));
}
__device__ __forceinline__ uint32_t pack_h2(float f0, float f1) {
    __half2 h = __floats2half2_rn(f0, f1);
    return *(uint32_t*)&h;
}

// ===========================================================================
// Fused fp32 -> fp16 converts. cvt16x3 also builds the RoPE table.
// ===========================================================================
__global__ __launch_bounds__(256)
void cvt16x3_kernel(const float* __restrict__ a, const float* __restrict__ b,
                    const float* __restrict__ c, __half* __restrict__ dst,
                    float2* __restrict__ tab, int n4)
{
    int idx = blockIdx.x * blockDim.x + threadIdx.x;
    if (idx < S_ * 32) {
        int s = idx >> 5;
        int d = idx & 31;
        double inv = exp(-log(10000.0) * (double)d / 32.0);
        double ang = (double)s * inv;
        double sd, cd;
        sincos(ang, &sd, &cd);
        tab[idx] = make_float2((float)cd, (float)sd);
    }
    if (idx >= 3 * n4) return;
    int sel = idx / n4;
    int i = idx - sel * n4;
    const float* x = (sel == 0) ? a : (sel == 1) ? b : c;
    float4 v = ((const float4*)x)[i];
    __half* o = dst + (size_t)sel * NTOT;
    ((uint32_t*)o)[2 * i + 0] = pack_h2(v.x, v.y);
    ((uint32_t*)o)[2 * i + 1] = pack_h2(v.z, v.w);
}

__global__ __launch_bounds__(256)
void cvt16x4w_kernel(const float* __restrict__ wq, const float* __restrict__ wk,
                     const float* __restrict__ wv, const float* __restrict__ wo,
                     __half* __restrict__ dqkv, __half* __restrict__ dwo, int n4)
{
    int idx = blockIdx.x * blockDim.x + threadIdx.x;
    if (idx >= 4 * n4) return;
    int sel = idx / n4;
    int i = idx - sel * n4;
    const float* x = (sel == 0) ? wq : (sel == 1) ? wk : (sel == 2) ? wv : wo;
    __half* o = (sel == 3) ? dwo : (dqkv + (size_t)sel * (D_ * D_));
    float4 v = ((const float4*)x)[i];
    ((uint32_t*)o)[2 * i + 0] = pack_h2(v.x, v.y);
    ((uint32_t*)o)[2 * i + 1] = pack_h2(v.z, v.w);
}

// ===========================================================================
// fp16 GEMM building blocks: 128x128 tile, BK=64, 3-stage cp.async, 2 CTA/SM.
// ===========================================================================
#define TILE_BYTES 16384                   // 128 rows x 128 B (128x64 fp16)
#define STAGE_BYTES (2 * TILE_BYTES)       // 32 KB (A + B)
#define GEMM_SMEM (3 * STAGE_BYTES)        // 96 KB -> 2 CTAs/SM
#define NCHUNK (D_ / 64)                   // 16
#define EPI_STRIDE 132                     // fp16 stride for epilogue tile

__device__ __forceinline__ void gemm_load_chunk(
    uint32_t sb, int stage, int k0, int tid,
    const __half* Ab, const __half* Bb)
{
    uint32_t base = sb + stage * STAGE_BYTES;
#pragma unroll
    for (int rep = 0; rep < 4; rep++) {
        int id  = tid + rep * 256;
        int row = id >> 3;
        int seg = id & 7;
        uint32_t soff = SMEM_SWIZZLE_128B((uint32_t)(row * 128 + seg * 16));
        size_t goff = (size_t)row * D_ + k0 + seg * 8;
        cpa16(base + 0 * TILE_BYTES + soff, Ab + goff);
        cpa16(base + 1 * TILE_BYTES + soff, Bb + goff);
    }
    asm volatile("cp.async.commit_group;" ::: "memory");
}

__device__ __forceinline__ void gemm_mainloop(
    uint32_t sb, int tid, const __half* Ab, const __half* Bb,
    int warp_m, int warp_n, int lane, float acc[4][4][4])
{
#pragma unroll
    for (int i = 0; i < 4; i++)
#pragma unroll
        for (int j = 0; j < 4; j++)
#pragma unroll
            for (int r = 0; r < 4; r++) acc[i][j][r] = 0.f;

    const int mat = lane >> 3;
    const int mrr = lane & 7;
    const int a_row_off = (mat & 1) * 8 + mrr;
    const int a_ks_off  = (mat >> 1) * 16;
    const int b_row_off = (mat >> 1) * 8 + mrr;
    const int b_ks_off  = (mat & 1) * 16;

    gemm_load_chunk(sb, 0, 0, tid, Ab, Bb);
    gemm_load_chunk(sb, 1, 64, tid, Ab, Bb);

    int stage = 0;
    for (int c = 0; c < NCHUNK; c++) {
        if (c + 1 < NCHUNK) {
            asm volatile("cp.async.wait_group 1;" ::: "memory");
        } else {
            asm volatile("cp.async.wait_group 0;" ::: "memory");
        }
        __syncthreads();

        if (c + 2 < NCHUNK) {
            int ls = stage + 2; if (ls >= 3) ls -= 3;
            gemm_load_chunk(sb, ls, (c + 2) * 64, tid, Ab, Bb);
        }

        uint32_t stA = sb + stage * STAGE_BYTES;
#pragma unroll
        for (int ks = 0; ks < 4; ks++) {
            const int kb = ks * 32;
            uint32_t ah[4][4];
#pragma unroll
            for (int mt = 0; mt < 4; mt++) {
                int row = warp_m * 64 + mt * 16 + a_row_off;
                uint32_t off = SMEM_SWIZZLE_128B((uint32_t)(row * 128 + kb + a_ks_off));
                ldsm4(ah[mt][0], ah[mt][1], ah[mt][2], ah[mt][3], stA + 0 * TILE_BYTES + off);
            }
            uint32_t bh[2][4];
#pragma unroll
            for (int p = 0; p < 2; p++) {
                int row = warp_n * 32 + p * 16 + b_row_off;
                uint32_t off = SMEM_SWIZZLE_128B((uint32_t)(row * 128 + kb + b_ks_off));
                ldsm4(bh[p][0], bh[p][1], bh[p][2], bh[p][3], stA + 1 * TILE_BYTES + off);
            }
#pragma unroll
            for (int mt = 0; mt < 4; mt++) {
#pragma unroll
                for (int p = 0; p < 2; p++) {
#pragma unroll
                    for (int q = 0; q < 2; q++) {
                        mma_fp16(acc[mt][p * 2 + q], ah[mt], bh[p][q * 2], bh[p][q * 2 + 1]);
                    }
                }
            }
        }
        stage++; if (stage >= 3) stage = 0;
    }
    __syncthreads();   // protect smem reuse by epilogue
}

// ---------------------------------------------------------------------------
// Fused QKV projection + RoPE-in-epilogue for Q/K. Q pre-scaled by
// log2(e)/sqrt(HD) so flash scores are in log2 domain.
// ---------------------------------------------------------------------------
__global__ __launch_bounds__(256, 2)
void gemm_qkv(const __half* __restrict__ X3, const __half* __restrict__ Wqkv,
              const float* __restrict__ bq, const float* __restrict__ bk,
              const float* __restrict__ bv, const float2* __restrict__ rope,
              __half* __restrict__ Qo, __half* __restrict__ Ko, __half* __restrict__ Vo)
{
    extern __shared__ char smem[];
    uint32_t sb = smem_to_u32(smem);
    const int tid  = threadIdx.x;
    const int wid  = tid >> 5;
    const int lane = tid & 31;
    const int warp_m = wid >> 2;
    const int warp_n = wid & 3;
    const int bn = blockIdx.x, bm = blockIdx.y;
    const int sel = bn >> 3;          // 0=Q, 1=K, 2=V
    const int bnl = bn & 7;

    const __half* Ab = X3 + (size_t)sel * NTOT + (size_t)(bm * 128) * D_;
    const __half* Bb = Wqkv + (size_t)sel * D_ * D_ + (size_t)(bnl * 128) * D_;
    const float* bias = (sel == 0) ? bq : (sel == 1) ? bk : bv;
    __half* Co = (sel == 0) ? Qo : (sel == 1) ? Ko : Vo;

    float acc[4][4][4];
    gemm_mainloop(sb, tid, Ab, Bb, warp_m, warp_n, lane, acc);

    const int rloc = warp_m * 64 + (lane >> 2);
    const int cloc = warp_n * 32 + (lane & 3) * 2;

    if (sel == 2) {
        const int rbase = bm * 128 + rloc;
        const int cbase = bnl * 128 + cloc;
#pragma unroll
        for (int mt = 0; mt < 4; mt++) {
#pragma unroll
            for (int nt = 0; nt < 4; nt++) {
                int col = cbase + nt * 8;
                float b0 = bias[col], b1 = bias[col + 1];
                float* d = acc[mt][nt];
                int r0 = rbase + mt * 16;
                *(uint32_t*)(Co + (size_t)r0 * D_ + col)       = pack_h2(d[0] + b0, d[1] + b1);
                *(uint32_t*)(Co + (size_t)(r0 + 8) * D_ + col) = pack_h2(d[2] + b0, d[3] + b1);
            }
        }
    } else {
        __half* T = (__half*)smem;
#pragma unroll
        for (int mt = 0; mt < 4; mt++) {
#pragma unroll
            for (int nt = 0; nt < 4; nt++) {
                int col = cloc + nt * 8;
                int gcol = bnl * 128 + col;
                float b0 = bias[gcol], b1 = bias[gcol + 1];
                float* d = acc[mt][nt];
                int r0 = rloc + mt * 16;
                *(uint32_t*)(T + (size_t)r0 * EPI_STRIDE + col)       = pack_h2(d[0] + b0, d[1] + b1);
                *(uint32_t*)(T + (size_t)(r0 + 8) * EPI_STRIDE + col) = pack_h2(d[2] + b0, d[3] + b1);
            }
        }
        __syncthreads();

        const float qs = (sel == 0) ? 0.125f * 1.4426950408889634f : 1.0f;
        for (int it = tid; it < 128 * 2 * 16; it += 256) {
            int dq  = it & 15;
            int hh  = (it >> 4) & 1;
            int row = it >> 5;
            int d   = dq * 2;
            int colA = hh * 64 + d;

            __half2 a2 = *(__half2*)(T + (size_t)row * EPI_STRIDE + colA);
            __half2 b2 = *(__half2*)(T + (size_t)row * EPI_STRIDE + colA + 32);
            float2 a = __half22float2(a2);
            float2 b = __half22float2(b2);

            int grow = bm * 128 + row;
            int s = grow & (S_ - 1);
            float2 t0 = rope[s * 32 + d];
            float2 t1 = rope[s * 32 + d + 1];

            float rx0 = fmaf(a.x, t0.x, -b.x * t0.y) * qs, ry0 = fmaf(a.x, t0.y, b.x * t0.x) * qs;
            float rx1 = fmaf(a.y, t1.x, -b.y * t1.y) * qs, ry1 = fmaf(a.y, t1.y, b.y * t1.x) * qs;

            size_t goff = (size_t)grow * D_ + bnl * 128 + colA;
            *(uint32_t*)(Co + goff)      = pack_h2(rx0, rx1);
            *(uint32_t*)(Co + goff + 32) = pack_h2(ry0, ry1);
        }
    }
}

// ---------------------------------------------------------------------------
// Output projection GEMM: fp16 in, fp32 out.
// ---------------------------------------------------------------------------
__global__ __launch_bounds__(256, 2)
void gemm_out(const __half* __restrict__ A, const __half* __restrict__ W,
              const float* __restrict__ bias, float* __restrict__ C)
{
    extern __shared__ char smem[];
    uint32_t sb = smem_to_u32(smem);
    const int tid  = threadIdx.x;
    const int wid  = tid >> 5;
    const int lane = tid & 31;
    const int warp_m = wid >> 2;
    const int warp_n = wid & 3;
    const int bn = blockIdx.x, bm = blockIdx.y;

    const __half* Ab = A + (size_t)(bm * 128) * D_;
    const __half* Bb = W + (size_t)(bn * 128) * D_;

    float acc[4][4][4];
    gemm_mainloop(sb, tid, Ab, Bb, warp_m, warp_n, lane, acc);

    const int rbase = bm * 128 + warp_m * 64 + (lane >> 2);
    const int cbase = bn * 128 + warp_n * 32 + (lane & 3) * 2;
#pragma unroll
    for (int mt = 0; mt < 4; mt++) {
#pragma unroll
        for (int nt = 0; nt < 4; nt++) {
            int col = cbase + nt * 8;
            float b0 = bias[col], b1 = bias[col + 1];
            float* d = acc[mt][nt];
            int r0 = rbase + mt * 16;
            *(float2*)(C + (size_t)r0 * D_ + col)       = make_float2(d[0] + b0, d[1] + b1);
            *(float2*)(C + (size_t)(r0 + 8) * D_ + col) = make_float2(d[2] + b0, d[3] + b1);
        }
    }
}

// ===========================================================================
// Tensor-core flash attention, all-fp16 MMA. BM=128.
// exp2 domain; ones-MMA row sums; bit-exact max-update skip.
// 128-row KV stages, two 64-wide sub-tiles per window, one sync/window.
// ===========================================================================
#define FQ 0
#define FST 16384
#define FK 0
#define FV 16384
#define FSTAGE 32768
#define FLASH_SMEM (16384 + 2 * FSTAGE)   // 81920 -> 2 CTA/SM
#define H2_ONES 0x3C003C00u

__device__ __forceinline__ void flash_load_kv128(
    uint32_t sb, int stage, int kt2, int tid,
    const __half* Kb, const __half* Vb)
{
    uint32_t base = sb + FST + stage * FSTAGE;
    size_t rbase = (size_t)(kt2 * 128) * D_;
#pragma unroll
    for (int rep = 0; rep < 4; rep++) {
        int id  = tid + rep * 256;
        int row = id >> 3;
        int seg = id & 7;
        uint32_t soff = SMEM_SWIZZLE_128B((uint32_t)(row * 128 + seg * 16));
        size_t goff = rbase + (size_t)row * D_ + seg * 8;
        cpa16(base + FK + soff, Kb + goff);
        cpa16(base + FV + soff, Vb + goff);
    }
    asm volatile("cp.async.commit_group;" ::: "memory");
}

__global__ __launch_bounds__(256, 2)
void flash_mma(const __half* __restrict__ Q_g, const __half* __restrict__ K_g,
               const __half* __restrict__ V_g, __half* __restrict__ O_g)
{
    extern __shared__ char smem[];
    uint32_t sb = smem_to_u32(smem);
    const int tid  = threadIdx.x;
    const int wid  = tid >> 5;
    const int lane = tid & 31;
    const int qt = (int)(gridDim.x - 1 - blockIdx.x);   // heavy tiles first
    const int h = blockIdx.y, b = blockIdx.z;

    const int g = lane >> 2, c = lane & 3;
    const int mat = lane >> 3, mrr = lane & 7;
    const int a_row_off = (mat & 1) * 8 + mrr;
    const int a_ks_off  = (mat >> 1) * 16;
    const int b_row_off = (mat >> 1) * 8 + mrr;
    const int b_ks_off  = (mat & 1) * 16;
    const int v_l = lane & 7, v_half = (lane >> 3) & 1, v_quad = lane >> 4;

    const size_t hoff = (size_t)(b * S_) * D_ + h * HD_;
    const __half* Qb = Q_g + hoff + (size_t)(qt * 128) * D_;
    const __half* Kb = K_g + hoff;
    const __half* Vb = V_g + hoff;

#pragma unroll
    for (int rep = 0; rep < 4; rep++) {
        int id  = tid + rep * 256;
        int row = id >> 3;
        int seg = id & 7;
        uint32_t soff = SMEM_SWIZZLE_128B((uint32_t)(row * 128 + seg * 16));
        size_t goff = (size_t)row * D_ + seg * 8;
        cpa16(sb + FQ + soff, Qb + goff);
    }
    asm volatile("cp.async.commit_group;" ::: "memory");

    flash_load_kv128(sb, 0, 0, tid, Kb, Vb);
    asm volatile("cp.async.wait_group 0;" ::: "memory");
    __syncthreads();

    uint32_t qf[4][4];
#pragma unroll
    for (int t = 0; t < 4; t++) {
        int rowA = wid * 16 + a_row_off;
        uint32_t off = SMEM_SWIZZLE_128B((uint32_t)(rowA * 128 + t * 32 + a_ks_off));
        ldsm4(qf[t][0], qf[t][1], qf[t][2], qf[t][3], sb + FQ + off);
    }

    float mi0 = -INFINITY, mi1 = -INFINITY, li0 = 0.f, li1 = 0.f;
    float o[8][4];
#pragma unroll
    for (int j = 0; j < 8; j++)
#pragma unroll
        for (int r = 0; r < 4; r++) o[j][r] = 0.f;

    const int wrow = qt * 128 + wid * 16;

    for (int kt2 = 0; kt2 <= qt; kt2++) {
        int s = kt2 & 1;
        if (kt2 > 0) {
            asm volatile("cp.async.wait_group 0;" ::: "memory");
            __syncthreads();
        }
        if (kt2 < qt) {
            flash_load_kv128(sb, s ^ 1, kt2 + 1, tid, Kb, Vb);
        }

        const uint32_t stK = sb + FST + s * FSTAGE + FK;
        const uint32_t stV = sb + FST + s * FSTAGE + FV;

#pragma unroll
        for (int sub = 0; sub < 2; sub++) {
            const int kbase = kt2 * 128 + sub * 64;
            if (kbase > wrow + 15) continue;

            float sc[8][4];
#pragma unroll
            for (int j = 0; j < 8; j++)
#pragma unroll
                for (int r = 0; r < 4; r++) sc[j][r] = 0.f;

#pragma unroll
            for (int t = 0; t < 4; t++) {
#pragma unroll
                for (int p = 0; p < 4; p++) {
                    uint32_t k4[4];
                    int rowB = sub * 64 + p * 16 + b_row_off;
                    uint32_t off = SMEM_SWIZZLE_128B((uint32_t)(rowB * 128 + t * 32 + b_ks_off));
                    ldsm4(k4[0], k4[1], k4[2], k4[3], stK + off);
                    mma_fp16(sc[2 * p],     qf[t], k4[0], k4[1]);
                    mma_fp16(sc[2 * p + 1], qf[t], k4[2], k4[3]);
                }
            }

            const int row0 = wrow + g, row1 = row0 + 8;
            if (kbase + 63 > wrow) {
#pragma unroll
                for (int j = 0; j < 8; j++) {
                    int col0 = kbase + j * 8 + 2 * c, col1 = col0 + 1;
                    if (col0 > row0) sc[j][0] = -INFINITY;
                    if (col1 > row0) sc[j][1] = -INFINITY;
                    if (col0 > row1) sc[j][2] = -INFINITY;
                    if (col1 > row1) sc[j][3] = -INFINITY;
                }
            }
            float rm0 = -INFINITY, rm1 = -INFINITY;
#pragma unroll
            for (int j = 0; j < 8; j++) {
                rm0 = fmaxf(rm0, fmaxf(sc[j][0], sc[j][1]));
                rm1 = fmaxf(rm1, fmaxf(sc[j][2], sc[j][3]));
            }
            rm0 = fmaxf(rm0, __shfl_xor_sync(0xffffffffu, rm0, 1));
            rm0 = fmaxf(rm0, __shfl_xor_sync(0xffffffffu, rm0, 2));
            rm1 = fmaxf(rm1, __shfl_xor_sync(0xffffffffu, rm1, 1));
            rm1 = fmaxf(rm1, __shfl_xor_sync(0xffffffffu, rm1, 2));

            // Bit-exact skip: if no lane's running max changes, al==1 exactly
            // and the rescale is the identity.
            bool noup = (rm0 <= mi0) && (rm1 <= mi1);
            if (!__all_sync(0xffffffffu, noup)) {
                float mn0 = fmaxf(mi0, rm0), mn1 = fmaxf(mi1, rm1);
                float al0 = exp2f(mi0 - mn0), al1 = exp2f(mi1 - mn1);
                mi0 = mn0; mi1 = mn1;
                li0 *= al0; li1 *= al1;
#pragma unroll
                for (int j = 0; j < 8; j++) {
                    o[j][0] *= al0; o[j][1] *= al0;
                    o[j][2] *= al1; o[j][3] *= al1;
                }
            }

#pragma unroll
            for (int j = 0; j < 8; j++) {
                sc[j][0] = exp2f(sc[j][0] - mi0);
                sc[j][1] = exp2f(sc[j][1] - mi0);
                sc[j][2] = exp2f(sc[j][2] - mi1);
                sc[j][3] = exp2f(sc[j][3] - mi1);
            }

            uint32_t ph[4][4];
#pragma unroll
            for (int t = 0; t < 4; t++) {
                ph[t][0] = pack_h2(sc[2 * t][0],     sc[2 * t][1]);
                ph[t][1] = pack_h2(sc[2 * t][2],     sc[2 * t][3]);
                ph[t][2] = pack_h2(sc[2 * t + 1][0], sc[2 * t + 1][1]);
                ph[t][3] = pack_h2(sc[2 * t + 1][2], sc[2 * t + 1][3]);
            }

            // Row-sums via ones-MMA
            float ssum[4] = {0.f, 0.f, 0.f, 0.f};
#pragma unroll
            for (int t = 0; t < 4; t++)
                mma_fp16(ssum, ph[t], H2_ONES, H2_ONES);
            li0 += ssum[0];
            li1 += ssum[2];

#pragma unroll
            for (int t = 0; t < 4; t++) {
#pragma unroll
                for (int jp = 0; jp < 4; jp++) {
                    uint32_t soff = SMEM_SWIZZLE_128B(
                        (uint32_t)((sub * 64 + 16 * t + v_half * 8 + v_l) * 128 + jp * 32 + v_quad * 16));
                    uint32_t v4[4];
                    ldsm4t(v4[0], v4[1], v4[2], v4[3], stV + soff);
                    mma_fp16(o[2 * jp],     ph[t], v4[0], v4[1]);
                    mma_fp16(o[2 * jp + 1], ph[t], v4[2], v4[3]);
                }
            }
        }
    }

    float iv0 = 1.f / li0, iv1 = 1.f / li1;
    size_t r0off = ((size_t)(b * S_ + wrow + g)) * D_ + h * HD_;
    size_t r1off = r0off + 8 * D_;
#pragma unroll
    for (int j = 0; j < 8; j++) {
        int col = j * 8 + 2 * c;
        *(uint32_t*)(O_g + r0off + col) = pack_h2(o[j][0] * iv0, o[j][1] * iv0);
        *(uint32_t*)(O_g + r1off + col) = pack_h2(o[j][2] * iv1, o[j][3] * iv1);
    }
}

// ---------------------------------------------------------------------------
extern "C" void kernel_launch(void* const* d_in, const int* in_sizes, int n_in,
                              void* d_out, int out_size)
{
    const float* Q  = (const float*)d_in[0];
    const float* K  = (const float*)d_in[1];
    const float* V  = (const float*)d_in[2];
    const float* Wq = (const float*)d_in[3];
    const float* bq = (const float*)d_in[4];
    const float* Wk = (const float*)d_in[5];
    const float* bk = (const float*)d_in[6];
    const float* Wv = (const float*)d_in[7];
    const float* bv = (const float*)d_in[8];
    const float* Wo = (const float*)d_in[9];
    const float* bo = (const float*)d_in[10];
    float* out = (float*)d_out;

    float2* grope;
    __half *gx3, *gwqkv, *gw16, *gq16, *gk16, *gv16, *go16;
    cudaGetSymbolAddress((void**)&grope, g_rope);
    cudaGetSymbolAddress((void**)&gx3, g_x3);
    cudaGetSymbolAddress((void**)&gwqkv, g_wqkv);
    cudaGetSymbolAddress((void**)&gw16, g_w16);
    cudaGetSymbolAddress((void**)&gq16, g_q16);
    cudaGetSymbolAddress((void**)&gk16, g_k16);
    cudaGetSymbolAddress((void**)&gv16, g_v16);
    cudaGetSymbolAddress((void**)&go16, g_o16);

    cudaFuncSetAttribute(gemm_qkv, cudaFuncAttributeMaxDynamicSharedMemorySize, GEMM_SMEM);
    cudaFuncSetAttribute(gemm_out, cudaFuncAttributeMaxDynamicSharedMemorySize, GEMM_SMEM);
    cudaFuncSetAttribute(flash_mma, cudaFuncAttributeMaxDynamicSharedMemorySize, FLASH_SMEM);

    const int n4x = NTOT / 4;
    const int n4w = (D_ * D_) / 4;

    cvt16x3_kernel<<<(3 * n4x + 255) / 256, 256>>>(Q, K, V, gx3, grope, n4x);
    cvt16x4w_kernel<<<(4 * n4w + 255) / 256, 256>>>(Wq, Wk, Wv, Wo, gwqkv, gw16, n4w);

    dim3 qkvgrid(3 * D_ / 128, M_ / 128);
    gemm_qkv<<<qkvgrid, 256, GEMM_SMEM>>>(gx3, gwqkv, bq, bk, bv, grope,
                                          gq16, gk16, gv16);

    dim3 fgrid(S_ / 128, H_, B_);
    flash_mma<<<fgrid, 256, FLASH_SMEM>>>(gq16, gk16, gv16, go16);

    dim3 ogrid(D_ / 128, M_ / 128);
    gemm_out<<<ogrid, 256, GEMM_SMEM>>>(go16, gw16, bo, out);
}